// round 5
// baseline (speedup 1.0000x reference)
#include <cuda_runtime.h>
#include <cuda_bf16.h>

#define N_NODES 60000
#define D 128
#define IN_RNN 257   // D + 1 + FEAT
#define ALPHA 0.1f

// Scratch (allocation-free rule: __device__ globals, referenced directly from
// kernels — no runtime API needed in kernel_launch).
__device__ float g_support[N_NODES * D];
__device__ float g_agg[N_NODES * D];
__device__ float g_x[N_NODES * D];

// ---------------------------------------------------------------------------
// GEMM: out[n, d] = sum_k X[n, k] * W[k, d]   (X: [N,128], W: [128,128])
// BM=64, BN=128 (full), BK=32, 256 threads, per-thread tile 8x4.
// ---------------------------------------------------------------------------
__global__ void gemm_kernel(const float* __restrict__ X,
                            const float* __restrict__ W,
                            float* __restrict__ out, int n_rows) {
    __shared__ float As[64][33];
    __shared__ float Bs[32][128];

    const int block_row = blockIdx.x * 64;
    const int t  = threadIdx.x;
    const int tc = t & 31;           // col group: cols tc*4 .. tc*4+3
    const int tr = t >> 5;           // row group: rows tr*8 .. tr*8+7

    float acc[8][4];
    #pragma unroll
    for (int i = 0; i < 8; i++)
        #pragma unroll
        for (int j = 0; j < 4; j++) acc[i][j] = 0.0f;

    for (int k0 = 0; k0 < 128; k0 += 32) {
        #pragma unroll
        for (int i = 0; i < 2; i++) {
            int idx = t + i * 256;       // float4 slot
            int r = idx >> 3;            // 8 float4 per row
            int c = (idx & 7) * 4;
            int grow = block_row + r;
            float4 v = make_float4(0.f, 0.f, 0.f, 0.f);
            if (grow < n_rows)
                v = *reinterpret_cast<const float4*>(&X[grow * 128 + k0 + c]);
            As[r][c + 0] = v.x; As[r][c + 1] = v.y;
            As[r][c + 2] = v.z; As[r][c + 3] = v.w;
        }
        #pragma unroll
        for (int i = 0; i < 4; i++) {
            int idx = t + i * 256;
            int r = idx >> 5;            // 32 float4 per row
            int c = (idx & 31) * 4;
            float4 v = *reinterpret_cast<const float4*>(&W[(k0 + r) * 128 + c]);
            *reinterpret_cast<float4*>(&Bs[r][c]) = v;
        }
        __syncthreads();

        #pragma unroll
        for (int kk = 0; kk < 32; kk++) {
            float a[8];
            #pragma unroll
            for (int i = 0; i < 8; i++) a[i] = As[tr * 8 + i][kk];
            float4 b = *reinterpret_cast<const float4*>(&Bs[kk][tc * 4]);
            #pragma unroll
            for (int i = 0; i < 8; i++) {
                acc[i][0] = fmaf(a[i], b.x, acc[i][0]);
                acc[i][1] = fmaf(a[i], b.y, acc[i][1]);
                acc[i][2] = fmaf(a[i], b.z, acc[i][2]);
                acc[i][3] = fmaf(a[i], b.w, acc[i][3]);
            }
        }
        __syncthreads();
    }

    #pragma unroll
    for (int i = 0; i < 8; i++) {
        int grow = block_row + tr * 8 + i;
        if (grow < n_rows) {
            float4 v = make_float4(acc[i][0], acc[i][1], acc[i][2], acc[i][3]);
            *reinterpret_cast<float4*>(&out[grow * 128 + tc * 4]) = v;
        }
    }
}

// GEMM wrappers binding scratch symbols (no cudaGetSymbolAddress needed)
__global__ void gemm1_kernel(const float* __restrict__ X,
                             const float* __restrict__ W, int n_rows);
__global__ void gemm2_kernel(const float* __restrict__ W, int n_rows);

// ---------------------------------------------------------------------------
// Zero agg buffer (float4)
// ---------------------------------------------------------------------------
__global__ void zero_kernel(int n4) {
    int i = blockIdx.x * blockDim.x + threadIdx.x;
    if (i < n4) reinterpret_cast<float4*>(g_agg)[i] = make_float4(0.f, 0.f, 0.f, 0.f);
}

// ---------------------------------------------------------------------------
// Edge scatter: g_agg[erow[e]] += eval[e] * g_support[ecol[e]]
// One warp per edge; lane handles 4 columns (float4 gather, 4 atomicAdds).
// ---------------------------------------------------------------------------
__global__ void scatter_kernel(const int* __restrict__ erow,
                               const int* __restrict__ ecol,
                               const float* __restrict__ eval_,
                               int n_edges) {
    int warp = (blockIdx.x * blockDim.x + threadIdx.x) >> 5;
    int lane = threadIdx.x & 31;
    if (warp >= n_edges) return;
    int col = ecol[warp];            // warp-uniform broadcast loads
    int row = erow[warp];
    float v  = eval_[warp];
    float4 s = *reinterpret_cast<const float4*>(&g_support[col * 128 + lane * 4]);
    float* dst = &g_agg[row * 128 + lane * 4];
    atomicAdd(dst + 0, s.x * v);
    atomicAdd(dst + 1, s.y * v);
    atomicAdd(dst + 2, s.z * v);
    atomicAdd(dst + 3, s.w * v);
}

// ---------------------------------------------------------------------------
// Blend + ReLU: g_x = relu(ALPHA * g_agg + (1-ALPHA) * init)
// ---------------------------------------------------------------------------
__global__ void blend_kernel(const float4* __restrict__ init, int n4) {
    int i = blockIdx.x * blockDim.x + threadIdx.x;
    if (i >= n4) return;
    float4 a = reinterpret_cast<const float4*>(g_agg)[i];
    float4 b = init[i];
    float4 r;
    r.x = fmaxf(ALPHA * a.x + (1.f - ALPHA) * b.x, 0.f);
    r.y = fmaxf(ALPHA * a.y + (1.f - ALPHA) * b.y, 0.f);
    r.z = fmaxf(ALPHA * a.z + (1.f - ALPHA) * b.z, 0.f);
    r.w = fmaxf(ALPHA * a.w + (1.f - ALPHA) * b.w, 0.f);
    reinterpret_cast<float4*>(g_x)[i] = r;
}

// ---------------------------------------------------------------------------
// GEMM entry points: layer1 reads external X -> g_support; layer2 reads g_x -> g_support
// ---------------------------------------------------------------------------
__global__ void __launch_bounds__(256) gemm1_launcher(const float* __restrict__ X,
                                                      const float* __restrict__ W,
                                                      int n_rows);

// To keep a single GEMM body, use a device function via templates instead:
template <int SRC>  // 0: external ptr, 1: g_x
__global__ void __launch_bounds__(256) gemm_t(const float* __restrict__ Xext,
                                              const float* __restrict__ W,
                                              int n_rows) {
    const float* X = (SRC == 0) ? Xext : g_x;
    __shared__ float As[64][33];
    __shared__ float Bs[32][128];

    const int block_row = blockIdx.x * 64;
    const int t  = threadIdx.x;
    const int tc = t & 31;
    const int tr = t >> 5;

    float acc[8][4];
    #pragma unroll
    for (int i = 0; i < 8; i++)
        #pragma unroll
        for (int j = 0; j < 4; j++) acc[i][j] = 0.0f;

    for (int k0 = 0; k0 < 128; k0 += 32) {
        #pragma unroll
        for (int i = 0; i < 2; i++) {
            int idx = t + i * 256;
            int r = idx >> 3;
            int c = (idx & 7) * 4;
            int grow = block_row + r;
            float4 v = make_float4(0.f, 0.f, 0.f, 0.f);
            if (grow < n_rows)
                v = *reinterpret_cast<const float4*>(&X[grow * 128 + k0 + c]);
            As[r][c + 0] = v.x; As[r][c + 1] = v.y;
            As[r][c + 2] = v.z; As[r][c + 3] = v.w;
        }
        #pragma unroll
        for (int i = 0; i < 4; i++) {
            int idx = t + i * 256;
            int r = idx >> 5;
            int c = (idx & 31) * 4;
            float4 v = *reinterpret_cast<const float4*>(&W[(k0 + r) * 128 + c]);
            *reinterpret_cast<float4*>(&Bs[r][c]) = v;
        }
        __syncthreads();

        #pragma unroll
        for (int kk = 0; kk < 32; kk++) {
            float a[8];
            #pragma unroll
            for (int i = 0; i < 8; i++) a[i] = As[tr * 8 + i][kk];
            float4 b = *reinterpret_cast<const float4*>(&Bs[kk][tc * 4]);
            #pragma unroll
            for (int i = 0; i < 8; i++) {
                acc[i][0] = fmaf(a[i], b.x, acc[i][0]);
                acc[i][1] = fmaf(a[i], b.y, acc[i][1]);
                acc[i][2] = fmaf(a[i], b.z, acc[i][2]);
                acc[i][3] = fmaf(a[i], b.w, acc[i][3]);
            }
        }
        __syncthreads();
    }

    #pragma unroll
    for (int i = 0; i < 8; i++) {
        int grow = block_row + tr * 8 + i;
        if (grow < n_rows) {
            float4 v = make_float4(acc[i][0], acc[i][1], acc[i][2], acc[i][3]);
            *reinterpret_cast<float4*>(&g_support[grow * 128 + tc * 4]) = v;
        }
    }
}

// ---------------------------------------------------------------------------
// RNNCell(tanh) + L2 normalize.
// One block per batch row (256 blocks x 128 threads); thread d computes h[b][d].
// ---------------------------------------------------------------------------
__global__ void rnn_norm_kernel(const float* __restrict__ patient,  // [P,128]
                                const float* __restrict__ td,       // [B,1]
                                const float* __restrict__ feat,     // [B,128]
                                const float* __restrict__ Wih,      // [128,257]
                                const float* __restrict__ bih,      // [128]
                                const float* __restrict__ Whh,      // [128,128]
                                const float* __restrict__ bhh,      // [128]
                                const int* __restrict__ codeid,     // [B]
                                const int* __restrict__ patientid,  // [1]
                                float* __restrict__ out) {          // [B,128]
    __shared__ float s_in[IN_RNN];
    __shared__ float s_ce[D];
    __shared__ float s_red[D];

    const int b = blockIdx.x;
    const int d = threadIdx.x;       // 0..127
    const int pid = patientid[0];

    s_in[d] = patient[pid * 128 + d];
    if (d == 0) s_in[128] = td[b];
    s_in[129 + d] = feat[b * 128 + d];
    const int cid = codeid[b];
    s_ce[d] = g_x[cid * 128 + d];
    __syncthreads();

    float acc = bih[d] + bhh[d];
    const float* wih = &Wih[d * IN_RNN];
    #pragma unroll 4
    for (int k = 0; k < IN_RNN; k++) acc = fmaf(s_in[k], wih[k], acc);
    const float* whh = &Whh[d * D];
    #pragma unroll 4
    for (int k = 0; k < D; k++) acc = fmaf(s_ce[k], whh[k], acc);

    float h = tanhf(acc);
    s_red[d] = h * h;
    __syncthreads();
    #pragma unroll
    for (int s = 64; s > 0; s >>= 1) {
        if (d < s) s_red[d] += s_red[d + s];
        __syncthreads();
    }
    float nrm = fmaxf(sqrtf(s_red[0]), 1e-12f);
    out[b * 128 + d] = h / nrm;
}

// ---------------------------------------------------------------------------
extern "C" void kernel_launch(void* const* d_in, const int* in_sizes, int n_in,
                              void* d_out, int out_size) {
    const float* code_dynamic = (const float*)d_in[0];
    const float* init_x       = (const float*)d_in[1];
    const float* patient      = (const float*)d_in[2];
    const float* timediffs    = (const float*)d_in[3];
    const float* features     = (const float*)d_in[4];
    const float* edge_val     = (const float*)d_in[5];
    const float* W1           = (const float*)d_in[6];
    const float* W2           = (const float*)d_in[7];
    const float* W_ih         = (const float*)d_in[8];
    const float* b_ih         = (const float*)d_in[9];
    const float* W_hh         = (const float*)d_in[10];
    const float* b_hh         = (const float*)d_in[11];
    const int*   edge_row     = (const int*)d_in[12];
    const int*   edge_col     = (const int*)d_in[13];
    const int*   codeid       = (const int*)d_in[14];
    const int*   patientid    = (const int*)d_in[15];
    float* out = (float*)d_out;

    const int n_nodes = in_sizes[0] / D;         // 60000
    const int n_edges = in_sizes[5];             // 600000
    const int batch   = in_sizes[14];            // 256

    const int n4 = n_nodes * D / 4;
    const int gemm_grid  = (n_nodes + 63) / 64;
    const int elem_grid  = (n4 + 255) / 256;
    const int scat_grid  = (n_edges * 32 + 255) / 256;

    // Layer 1
    gemm_t<0><<<gemm_grid, 256>>>(code_dynamic, W1, n_nodes);
    zero_kernel<<<elem_grid, 256>>>(n4);
    scatter_kernel<<<scat_grid, 256>>>(edge_row, edge_col, edge_val, n_edges);
    blend_kernel<<<elem_grid, 256>>>((const float4*)init_x, n4);

    // Layer 2
    gemm_t<1><<<gemm_grid, 256>>>(nullptr, W2, n_nodes);
    zero_kernel<<<elem_grid, 256>>>(n4);
    scatter_kernel<<<scat_grid, 256>>>(edge_row, edge_col, edge_val, n_edges);
    blend_kernel<<<elem_grid, 256>>>((const float4*)init_x, n4);

    // RNN + normalize
    rnn_norm_kernel<<<batch, 128>>>(patient, timediffs, features,
                                    W_ih, b_ih, W_hh, b_hh, codeid, patientid, out);
}

// round 8
// speedup vs baseline: 1.5310x; 1.5310x over previous
#include <cuda_runtime.h>
#include <cuda_bf16.h>

#define N_NODES 60000
#define D 128
#define IN_RNN 257   // D + 1 + FEAT
#define ALPHA 0.1f

// Scratch (allocation-free rule: __device__ globals)
__device__ float g_support[N_NODES * D];
__device__ float g_agg[N_NODES * D];
__device__ float g_x[N_NODES * D];

// ---------------------------------------------------------------------------
// GEMM: g_support[n, d] = sum_k X[n, k] * W[k, d]
// BM=64, BN=128, BK=32, 256 threads, per-thread tile 8x4.
// SRC==0: X = external pointer; SRC==1: X = g_x
// ---------------------------------------------------------------------------
template <int SRC>
__global__ void __launch_bounds__(256) gemm_t(const float* __restrict__ Xext,
                                              const float* __restrict__ W,
                                              int n_rows) {
    const float* X = (SRC == 0) ? Xext : g_x;
    __shared__ float As[64][33];
    __shared__ float Bs[32][128];

    const int block_row = blockIdx.x * 64;
    const int t  = threadIdx.x;
    const int tc = t & 31;
    const int tr = t >> 5;

    float acc[8][4];
    #pragma unroll
    for (int i = 0; i < 8; i++)
        #pragma unroll
        for (int j = 0; j < 4; j++) acc[i][j] = 0.0f;

    for (int k0 = 0; k0 < 128; k0 += 32) {
        #pragma unroll
        for (int i = 0; i < 2; i++) {
            int idx = t + i * 256;
            int r = idx >> 3;
            int c = (idx & 7) * 4;
            int grow = block_row + r;
            float4 v = make_float4(0.f, 0.f, 0.f, 0.f);
            if (grow < n_rows)
                v = *reinterpret_cast<const float4*>(&X[grow * 128 + k0 + c]);
            As[r][c + 0] = v.x; As[r][c + 1] = v.y;
            As[r][c + 2] = v.z; As[r][c + 3] = v.w;
        }
        #pragma unroll
        for (int i = 0; i < 4; i++) {
            int idx = t + i * 256;
            int r = idx >> 5;
            int c = (idx & 31) * 4;
            float4 v = *reinterpret_cast<const float4*>(&W[(k0 + r) * 128 + c]);
            *reinterpret_cast<float4*>(&Bs[r][c]) = v;
        }
        __syncthreads();

        #pragma unroll
        for (int kk = 0; kk < 32; kk++) {
            float a[8];
            #pragma unroll
            for (int i = 0; i < 8; i++) a[i] = As[tr * 8 + i][kk];
            float4 b = *reinterpret_cast<const float4*>(&Bs[kk][tc * 4]);
            #pragma unroll
            for (int i = 0; i < 8; i++) {
                acc[i][0] = fmaf(a[i], b.x, acc[i][0]);
                acc[i][1] = fmaf(a[i], b.y, acc[i][1]);
                acc[i][2] = fmaf(a[i], b.z, acc[i][2]);
                acc[i][3] = fmaf(a[i], b.w, acc[i][3]);
            }
        }
        __syncthreads();
    }

    #pragma unroll
    for (int i = 0; i < 8; i++) {
        int grow = block_row + tr * 8 + i;
        if (grow < n_rows) {
            float4 v = make_float4(acc[i][0], acc[i][1], acc[i][2], acc[i][3]);
            *reinterpret_cast<float4*>(&g_support[grow * 128 + tc * 4]) = v;
        }
    }
}

// ---------------------------------------------------------------------------
// Zero agg buffer (float4) — only needed before the first scatter
// ---------------------------------------------------------------------------
__global__ void zero_kernel(int n4) {
    int i = blockIdx.x * blockDim.x + threadIdx.x;
    if (i < n4) reinterpret_cast<float4*>(g_agg)[i] = make_float4(0.f, 0.f, 0.f, 0.f);
}

// ---------------------------------------------------------------------------
// Edge scatter: g_agg[erow[e]] += eval[e] * g_support[ecol[e]]
// One warp per edge; lane handles 4 columns via ONE red.global.add.v4.f32.
// ---------------------------------------------------------------------------
__global__ void scatter_kernel(const int* __restrict__ erow,
                               const int* __restrict__ ecol,
                               const float* __restrict__ eval_,
                               int n_edges) {
    int warp = (blockIdx.x * blockDim.x + threadIdx.x) >> 5;
    int lane = threadIdx.x & 31;
    if (warp >= n_edges) return;
    int col = ecol[warp];            // warp-uniform broadcast loads
    int row = erow[warp];
    float v  = eval_[warp];
    float4 s = *reinterpret_cast<const float4*>(&g_support[col * 128 + lane * 4]);
    float* dst = &g_agg[row * 128 + lane * 4];
    asm volatile("red.global.add.v4.f32 [%0], {%1, %2, %3, %4};"
                 :: "l"(dst), "f"(s.x * v), "f"(s.y * v), "f"(s.z * v), "f"(s.w * v)
                 : "memory");
}

// ---------------------------------------------------------------------------
// Blend + ReLU + re-zero agg for next scatter:
//   g_x = relu(ALPHA * g_agg + (1-ALPHA) * init);  g_agg = 0
// ---------------------------------------------------------------------------
__global__ void blend_kernel(const float4* __restrict__ init, int n4) {
    int i = blockIdx.x * blockDim.x + threadIdx.x;
    if (i >= n4) return;
    float4 a = reinterpret_cast<const float4*>(g_agg)[i];
    float4 b = init[i];
    float4 r;
    r.x = fmaxf(ALPHA * a.x + (1.f - ALPHA) * b.x, 0.f);
    r.y = fmaxf(ALPHA * a.y + (1.f - ALPHA) * b.y, 0.f);
    r.z = fmaxf(ALPHA * a.z + (1.f - ALPHA) * b.z, 0.f);
    r.w = fmaxf(ALPHA * a.w + (1.f - ALPHA) * b.w, 0.f);
    reinterpret_cast<float4*>(g_x)[i] = r;
    reinterpret_cast<float4*>(g_agg)[i] = make_float4(0.f, 0.f, 0.f, 0.f);
}

// ---------------------------------------------------------------------------
// RNNCell(tanh) + L2 normalize. One block per batch row.
// ---------------------------------------------------------------------------
__global__ void rnn_norm_kernel(const float* __restrict__ patient,  // [P,128]
                                const float* __restrict__ td,       // [B,1]
                                const float* __restrict__ feat,     // [B,128]
                                const float* __restrict__ Wih,      // [128,257]
                                const float* __restrict__ bih,      // [128]
                                const float* __restrict__ Whh,      // [128,128]
                                const float* __restrict__ bhh,      // [128]
                                const int* __restrict__ codeid,     // [B]
                                const int* __restrict__ patientid,  // [1]
                                float* __restrict__ out) {          // [B,128]
    __shared__ float s_in[IN_RNN];
    __shared__ float s_ce[D];
    __shared__ float s_red[D];

    const int b = blockIdx.x;
    const int d = threadIdx.x;       // 0..127
    const int pid = patientid[0];

    s_in[d] = patient[pid * 128 + d];
    if (d == 0) s_in[128] = td[b];
    s_in[129 + d] = feat[b * 128 + d];
    const int cid = codeid[b];
    s_ce[d] = g_x[cid * 128 + d];
    __syncthreads();

    float acc = bih[d] + bhh[d];
    const float* wih = &Wih[d * IN_RNN];
    #pragma unroll 4
    for (int k = 0; k < IN_RNN; k++) acc = fmaf(s_in[k], wih[k], acc);
    const float* whh = &Whh[d * D];
    #pragma unroll 4
    for (int k = 0; k < D; k++) acc = fmaf(s_ce[k], whh[k], acc);

    float h = tanhf(acc);
    s_red[d] = h * h;
    __syncthreads();
    #pragma unroll
    for (int s = 64; s > 0; s >>= 1) {
        if (d < s) s_red[d] += s_red[d + s];
        __syncthreads();
    }
    float nrm = fmaxf(sqrtf(s_red[0]), 1e-12f);
    out[b * 128 + d] = h / nrm;
}

// ---------------------------------------------------------------------------
extern "C" void kernel_launch(void* const* d_in, const int* in_sizes, int n_in,
                              void* d_out, int out_size) {
    const float* code_dynamic = (const float*)d_in[0];
    const float* init_x       = (const float*)d_in[1];
    const float* patient      = (const float*)d_in[2];
    const float* timediffs    = (const float*)d_in[3];
    const float* features     = (const float*)d_in[4];
    const float* edge_val     = (const float*)d_in[5];
    const float* W1           = (const float*)d_in[6];
    const float* W2           = (const float*)d_in[7];
    const float* W_ih         = (const float*)d_in[8];
    const float* b_ih         = (const float*)d_in[9];
    const float* W_hh         = (const float*)d_in[10];
    const float* b_hh         = (const float*)d_in[11];
    const int*   edge_row     = (const int*)d_in[12];
    const int*   edge_col     = (const int*)d_in[13];
    const int*   codeid       = (const int*)d_in[14];
    const int*   patientid    = (const int*)d_in[15];
    float* out = (float*)d_out;

    const int n_nodes = in_sizes[0] / D;         // 60000
    const int n_edges = in_sizes[5];             // 600000
    const int batch   = in_sizes[14];            // 256

    const int n4 = n_nodes * D / 4;
    const int gemm_grid  = (n_nodes + 63) / 64;
    const int elem_grid  = (n4 + 255) / 256;
    const int scat_grid  = (n_edges * 32 + 255) / 256;

    // Layer 1
    gemm_t<0><<<gemm_grid, 256>>>(code_dynamic, W1, n_nodes);
    zero_kernel<<<elem_grid, 256>>>(n4);
    scatter_kernel<<<scat_grid, 256>>>(edge_row, edge_col, edge_val, n_edges);
    blend_kernel<<<elem_grid, 256>>>((const float4*)init_x, n4);   // also re-zeros agg

    // Layer 2
    gemm_t<1><<<gemm_grid, 256>>>(nullptr, W2, n_nodes);
    scatter_kernel<<<scat_grid, 256>>>(edge_row, edge_col, edge_val, n_edges);
    blend_kernel<<<elem_grid, 256>>>((const float4*)init_x, n4);   // leaves agg zeroed

    // RNN + normalize
    rnn_norm_kernel<<<batch, 128>>>(patient, timediffs, features,
                                    W_ih, b_ih, W_hh, b_hh, codeid, patientid, out);
}